// round 16
// baseline (speedup 1.0000x reference)
#include <cuda_runtime.h>
#include <cstdint>

#define D_MODEL 1024
#define D_STATE 16
#define BATCH   4
#define SEQLEN  4096
#define NROWS   (BATCH*SEQLEN)      // 16384
#define CHUNK2  32
#define NCHUNK2 (SEQLEN/CHUNK2)     // 128
#define ESPLIT  8
#define EB      (D_MODEL/ESPLIT)    // 128 e's per block in K1

// ---------------- device scratch (no allocations allowed) ----------------
__device__ float g_bxp  [ESPLIT][NROWS * D_STATE]; // 8 MB partials
__device__ float g_bx   [NROWS * D_STATE];         // 1 MB
__device__ float g_decay[NROWS * D_STATE];         // 1 MB
__device__ float g_ca   [BATCH * NCHUNK2 * D_STATE];
__device__ float g_cv   [BATCH * NCHUNK2 * D_STATE];
__device__ float g_h0   [BATCH * NCHUNK2 * D_STATE];

// ---------------- f32x2 helpers ----------------
static __device__ __forceinline__ unsigned long long pack2(float lo, float hi) {
    unsigned long long r;
    asm("mov.b64 %0, {%1, %2};" : "=l"(r) : "f"(lo), "f"(hi));
    return r;
}
static __device__ __forceinline__ void unpack2(unsigned long long v, float& lo, float& hi) {
    asm("mov.b64 {%0, %1}, %2;" : "=f"(lo), "=f"(hi) : "l"(v));
}
static __device__ __forceinline__ unsigned long long fma2(unsigned long long a, unsigned long long b, unsigned long long c) {
    unsigned long long d;
    asm("fma.rn.f32x2 %0, %1, %2, %3;" : "=l"(d) : "l"(a), "l"(b), "l"(c));
    return d;
}
static __device__ __forceinline__ unsigned long long mul2(unsigned long long a, unsigned long long b) {
    unsigned long long d;
    asm("mul.rn.f32x2 %0, %1, %2;" : "=l"(d) : "l"(a), "l"(b));
    return d;
}
static __device__ __forceinline__ unsigned long long add2(unsigned long long a, unsigned long long b) {
    unsigned long long d;
    asm("add.rn.f32x2 %0, %1, %2;" : "=l"(d) : "l"(a), "l"(b));
    return d;
}

// =======================================================================
// K1: partial Bx over e-slice. grid (64, 8), block 256 (8 warps).
// =======================================================================
__global__ void __launch_bounds__(256, 4) k_bx(const float* __restrict__ x,
                                               const float* __restrict__ Bin)
{
    __shared__ float sB[EB * D_STATE];   // 8 KB
    __shared__ float xt[8][32 * 32];     // 32 KB

    const int tid  = threadIdx.x;
    const int w    = tid >> 5;
    const int lane = tid & 31;
    const int eBase   = blockIdx.y * EB;
    const int rowBase = blockIdx.x * 256 + w * 32;

    {
        const float4* B4 = (const float4*)(Bin + eBase * D_STATE);
        float4* sB4 = (float4*)sB;
        #pragma unroll
        for (int i = tid; i < EB * 4; i += 256) sB4[i] = B4[i];
    }
    __syncthreads();

    unsigned long long acc[8];
    #pragma unroll
    for (int j = 0; j < 8; j++) acc[j] = 0ull;

    const ulonglong2* sBu = (const ulonglong2*)sB;
    const float4* x4 = (const float4*)x;
    float* xtw = xt[w];

    const int rlo = lane >> 3;
    const int c4  = (lane & 7) * 4;

    #pragma unroll
    for (int t = 0; t < 4; t++) {
        const int eb4 = (eBase >> 2) + t * 8;
        __syncwarp();
        #pragma unroll
        for (int j = 0; j < 8; j++) {
            int rr = j * 4 + rlo;
            float4 xv = __ldg(x4 + (size_t)(rowBase + rr) * 256 + eb4 + (lane & 7));
            xtw[(c4 + 0) * 32 + (rr ^ (c4 + 0))] = xv.x;
            xtw[(c4 + 1) * 32 + (rr ^ (c4 + 1))] = xv.y;
            xtw[(c4 + 2) * 32 + (rr ^ (c4 + 2))] = xv.z;
            xtw[(c4 + 3) * 32 + (rr ^ (c4 + 3))] = xv.w;
        }
        __syncwarp();
        #pragma unroll
        for (int el = 0; el < 32; el++) {
            float xv = xtw[el * 32 + (lane ^ el)];
            unsigned long long xx = pack2(xv, xv);
            int e = t * 32 + el;
            ulonglong2 q0 = sBu[e * 4 + 0];
            ulonglong2 q1 = sBu[e * 4 + 1];
            ulonglong2 q2 = sBu[e * 4 + 2];
            ulonglong2 q3 = sBu[e * 4 + 3];
            acc[0] = fma2(q0.x, xx, acc[0]);
            acc[1] = fma2(q0.y, xx, acc[1]);
            acc[2] = fma2(q1.x, xx, acc[2]);
            acc[3] = fma2(q1.y, xx, acc[3]);
            acc[4] = fma2(q2.x, xx, acc[4]);
            acc[5] = fma2(q2.y, xx, acc[5]);
            acc[6] = fma2(q3.x, xx, acc[6]);
            acc[7] = fma2(q3.y, xx, acc[7]);
        }
    }

    const int row = rowBase + lane;
    float v[16];
    #pragma unroll
    for (int j = 0; j < 8; j++) unpack2(acc[j], v[2 * j], v[2 * j + 1]);
    float4* gp = (float4*)(&g_bxp[blockIdx.y][row * D_STATE]);
    #pragma unroll
    for (int q = 0; q < 4; q++)
        gp[q] = make_float4(v[4 * q], v[4 * q + 1], v[4 * q + 2], v[4 * q + 3]);
}

// =======================================================================
// K1.5: sum partials, softplus, decay, AND per-chunk aggregates.
// =======================================================================
__global__ void __launch_bounds__(256) k_combine(const float* __restrict__ A)
{
    __shared__ float sbx[64 * 16 + 16];
    __shared__ float sdc[64 * 16 + 16];

    const int tid = threadIdx.x;
    const int idx = blockIdx.x * 256 + tid;   // float4 index
    float4 s = make_float4(0.f, 0.f, 0.f, 0.f);
    #pragma unroll
    for (int p = 0; p < ESPLIT; p++) {
        float4 v = __ldg((const float4*)g_bxp[p] + idx);
        s.x += v.x; s.y += v.y; s.z += v.z; s.w += v.w;
    }
    const int q = (idx & 3) * 4;
    float4 d;
    {
        float a0 = -expf(__ldg(A + q + 0));
        float a1 = -expf(__ldg(A + q + 1));
        float a2 = -expf(__ldg(A + q + 2));
        float a3 = -expf(__ldg(A + q + 3));
        float sp;
        sp = fmaxf(s.x, 0.f) + log1pf(expf(-fabsf(s.x))); d.x = expf(sp * a0);
        sp = fmaxf(s.y, 0.f) + log1pf(expf(-fabsf(s.y))); d.y = expf(sp * a1);
        sp = fmaxf(s.z, 0.f) + log1pf(expf(-fabsf(s.z))); d.z = expf(sp * a2);
        sp = fmaxf(s.w, 0.f) + log1pf(expf(-fabsf(s.w))); d.w = expf(sp * a3);
    }
    ((float4*)g_bx)[idx]    = s;
    ((float4*)g_decay)[idx] = d;

    const int rl  = tid >> 2;
    const int off = rl * 16 + ((tid & 3) * 4) + (rl >= 32 ? 16 : 0);
    *(float4*)&sbx[off] = s;
    *(float4*)&sdc[off] = d;
    __syncthreads();

    if (tid < 32) {
        const int cl = tid >> 4;
        const int st = tid & 15;
        const int base = cl * (32 * 16 + 16) + st;
        float a = 1.0f, v = 0.0f;
        #pragma unroll 8
        for (int t = 0; t < CHUNK2; t++) {
            float dd = sdc[base + t * 16];
            float bb = sbx[base + t * 16];
            v = fmaf(v, dd, bb);
            a *= dd;
        }
        const int r0 = blockIdx.x * 64;
        const int b  = r0 >> 12;
        const int cc = ((r0 & (SEQLEN - 1)) >> 5) + cl;
        const int gi = (b * NCHUNK2 + cc) * 16 + st;
        g_ca[gi] = a;
        g_cv[gi] = v;
    }
}

// =======================================================================
// K2b: boundary scan, 1 block per batch; smem-staged serial chain.
// =======================================================================
__global__ void __launch_bounds__(256) k_scan2()
{
    __shared__ float sa[NCHUNK2 * D_STATE];   // 8 KB
    __shared__ float sv[NCHUNK2 * D_STATE];   // 8 KB
    const int b   = blockIdx.x;
    const int tid = threadIdx.x;

    const float4* ga = (const float4*)(g_ca + b * NCHUNK2 * D_STATE);
    const float4* gv = (const float4*)(g_cv + b * NCHUNK2 * D_STATE);
    #pragma unroll
    for (int i = tid; i < (NCHUNK2 * D_STATE) / 4; i += 256) {
        ((float4*)sa)[i] = __ldg(ga + i);
        ((float4*)sv)[i] = __ldg(gv + i);
    }
    __syncthreads();

    if (tid < 16) {
        const int base = b * NCHUNK2 * D_STATE + tid;
        float h = 0.0f;
        #pragma unroll 8
        for (int cc = 0; cc < NCHUNK2; cc++) {
            g_h0[base + cc * D_STATE] = h;
            h = fmaf(sa[cc * D_STATE + tid], h, sv[cc * D_STATE + tid]);
        }
    }
}

// =======================================================================
// K3: per-chunk local scan + y = h @ C + x*D
// grid 1024 x 256; 2 cols/thread. h is stored DUPLICATED in smem
// ((h,h) pairs) so the GEMM loop needs no pack2 MOVs: 8 broadcast
// LDS.128 + 16 fma2 per t (R13 evidence: 42 instrs/t, issue-count bound).
// =======================================================================
__global__ void __launch_bounds__(256, 4) k_out(const float* __restrict__ x,
                                                const float* __restrict__ C,
                                                const float* __restrict__ D,
                                                float* __restrict__ y)
{
    __shared__ __align__(16) float hh2[CHUNK2][32];   // (h,h) pairs, 4 KB
    const int idx  = blockIdx.x;
    const int half = idx & 1;
    const int c    = (idx >> 1) & 127;
    const int b    = idx >> 8;
    const int tid  = threadIdx.x;
    const int row0 = b * SEQLEN + c * CHUNK2;
    const int col0 = half * 512 + tid * 2;

    // ---- issue scan loads FIRST (overlap with C-tile load latency) ----
    float h = 0.0f, dA[8], vA[8];
    int sbase = 0;
    if (tid < 16) {
        h = g_h0[(b * NCHUNK2 + c) * 16 + tid];
        sbase = row0 * D_STATE + tid;
        #pragma unroll
        for (int k = 0; k < 8; k++) {
            dA[k] = g_decay[sbase + k * 16];
            vA[k] = g_bx   [sbase + k * 16];
        }
    }

    // C tile: 16 states x 2 cols -> 16 f32x2 regs
    unsigned long long ca[16];
    #pragma unroll
    for (int s = 0; s < 16; s++) {
        float2 cv = __ldg((const float2*)(C + s * D_MODEL + col0));
        ca[s] = pack2(cv.x, cv.y);
    }
    float2 dv = __ldg((const float2*)(D + col0));
    bool anyD = (dv.x != 0.0f) || (dv.y != 0.0f);
    unsigned long long d01 = pack2(dv.x, dv.y);

    // local 32-step scan by lanes 0..15; store (h,h) pairs (STS.64)
    if (tid < 16) {
        float dB[8], vB[8];
        #pragma unroll
        for (int g = 0; g < 4; g++) {
            if (g < 3) {
                #pragma unroll
                for (int k = 0; k < 8; k++) {
                    dB[k] = g_decay[sbase + ((g + 1) * 8 + k) * 16];
                    vB[k] = g_bx   [sbase + ((g + 1) * 8 + k) * 16];
                }
            }
            #pragma unroll
            for (int k = 0; k < 8; k++) {
                h = fmaf(h, dA[k], vA[k]);
                *reinterpret_cast<unsigned long long*>(&hh2[g * 8 + k][tid * 2]) = pack2(h, h);
            }
            #pragma unroll
            for (int k = 0; k < 8; k++) { dA[k] = dB[k]; vA[k] = vB[k]; }
        }
    }
    __syncthreads();

    #pragma unroll 2
    for (int t = 0; t < CHUNK2; t++) {
        unsigned long long p0, p1, p2, p3;
        if (anyD) {
            float2 xv = __ldg((const float2*)(x + (size_t)(row0 + t) * D_MODEL + col0));
            p0 = mul2(pack2(xv.x, xv.y), d01);
        } else {
            p0 = 0ull;
        }
        p1 = 0ull; p2 = 0ull; p3 = 0ull;

        const ulonglong2* hp = (const ulonglong2*)hh2[t];  // broadcast LDS.128

        ulonglong2 qa = hp[0];        // states 0,1 (duplicated pairs)
        ulonglong2 qb = hp[1];        // states 2,3
        p0 = fma2(qa.x, ca[0],  p0);
        p1 = fma2(qa.y, ca[1],  p1);
        p2 = fma2(qb.x, ca[2],  p2);
        p3 = fma2(qb.y, ca[3],  p3);
        qa = hp[2]; qb = hp[3];       // states 4..7
        p0 = fma2(qa.x, ca[4],  p0);
        p1 = fma2(qa.y, ca[5],  p1);
        p2 = fma2(qb.x, ca[6],  p2);
        p3 = fma2(qb.y, ca[7],  p3);
        qa = hp[4]; qb = hp[5];       // states 8..11
        p0 = fma2(qa.x, ca[8],  p0);
        p1 = fma2(qa.y, ca[9],  p1);
        p2 = fma2(qb.x, ca[10], p2);
        p3 = fma2(qb.y, ca[11], p3);
        qa = hp[6]; qb = hp[7];       // states 12..15
        p0 = fma2(qa.x, ca[12], p0);
        p1 = fma2(qa.y, ca[13], p1);
        p2 = fma2(qb.x, ca[14], p2);
        p3 = fma2(qb.y, ca[15], p3);

        unsigned long long y01 = add2(add2(p0, p1), add2(p2, p3));

        float2 out;
        unpack2(y01, out.x, out.y);
        *(float2*)(y + (size_t)(row0 + t) * D_MODEL + col0) = out;
    }
}

// =======================================================================
extern "C" void kernel_launch(void* const* d_in, const int* in_sizes, int n_in,
                              void* d_out, int out_size)
{
    const float* x   = (const float*)d_in[0];
    const float* A   = (const float*)d_in[1];
    const float* Bin = (const float*)d_in[2];
    const float* C   = (const float*)d_in[3];
    const float* D   = (const float*)d_in[4];
    float* y = (float*)d_out;

    dim3 g1(NROWS / 256, ESPLIT);
    k_bx<<<g1, 256>>>(x, Bin);
    k_combine<<<(NROWS * 4) / 256, 256>>>(A);
    k_scan2<<<BATCH, 256>>>();
    k_out<<<BATCH * NCHUNK2 * 2, 256>>>(x, C, D, y);
}

// round 17
// speedup vs baseline: 1.0697x; 1.0697x over previous
#include <cuda_runtime.h>
#include <cstdint>

#define D_MODEL 1024
#define D_STATE 16
#define BATCH   4
#define SEQLEN  4096
#define NROWS   (BATCH*SEQLEN)      // 16384
#define CHUNK2  32
#define NCHUNK2 (SEQLEN/CHUNK2)     // 128
#define ESPLIT  8
#define EB      (D_MODEL/ESPLIT)    // 128 e's per block in K1

// ---------------- device scratch (no allocations allowed) ----------------
__device__ float g_bxp  [ESPLIT][NROWS * D_STATE]; // 8 MB partials
__device__ float g_bx   [NROWS * D_STATE];         // 1 MB
__device__ float g_decay[NROWS * D_STATE];         // 1 MB
__device__ float g_ca   [BATCH * NCHUNK2 * D_STATE];
__device__ float g_cv   [BATCH * NCHUNK2 * D_STATE];
__device__ float g_h0   [BATCH * NCHUNK2 * D_STATE];

// ---------------- f32x2 helpers ----------------
static __device__ __forceinline__ unsigned long long pack2(float lo, float hi) {
    unsigned long long r;
    asm("mov.b64 %0, {%1, %2};" : "=l"(r) : "f"(lo), "f"(hi));
    return r;
}
static __device__ __forceinline__ void unpack2(unsigned long long v, float& lo, float& hi) {
    asm("mov.b64 {%0, %1}, %2;" : "=f"(lo), "=f"(hi) : "l"(v));
}
static __device__ __forceinline__ unsigned long long fma2(unsigned long long a, unsigned long long b, unsigned long long c) {
    unsigned long long d;
    asm("fma.rn.f32x2 %0, %1, %2, %3;" : "=l"(d) : "l"(a), "l"(b), "l"(c));
    return d;
}
static __device__ __forceinline__ unsigned long long mul2(unsigned long long a, unsigned long long b) {
    unsigned long long d;
    asm("mul.rn.f32x2 %0, %1, %2;" : "=l"(d) : "l"(a), "l"(b));
    return d;
}
static __device__ __forceinline__ unsigned long long add2(unsigned long long a, unsigned long long b) {
    unsigned long long d;
    asm("add.rn.f32x2 %0, %1, %2;" : "=l"(d) : "l"(a), "l"(b));
    return d;
}

// =======================================================================
// K1: partial Bx over e-slice. grid (64, 8), block 256 (8 warps).
// =======================================================================
__global__ void __launch_bounds__(256, 4) k_bx(const float* __restrict__ x,
                                               const float* __restrict__ Bin)
{
    __shared__ float sB[EB * D_STATE];   // 8 KB
    __shared__ float xt[8][32 * 32];     // 32 KB

    const int tid  = threadIdx.x;
    const int w    = tid >> 5;
    const int lane = tid & 31;
    const int eBase   = blockIdx.y * EB;
    const int rowBase = blockIdx.x * 256 + w * 32;

    {
        const float4* B4 = (const float4*)(Bin + eBase * D_STATE);
        float4* sB4 = (float4*)sB;
        #pragma unroll
        for (int i = tid; i < EB * 4; i += 256) sB4[i] = B4[i];
    }
    __syncthreads();

    unsigned long long acc[8];
    #pragma unroll
    for (int j = 0; j < 8; j++) acc[j] = 0ull;

    const ulonglong2* sBu = (const ulonglong2*)sB;
    const float4* x4 = (const float4*)x;
    float* xtw = xt[w];

    const int rlo = lane >> 3;
    const int c4  = (lane & 7) * 4;

    #pragma unroll
    for (int t = 0; t < 4; t++) {
        const int eb4 = (eBase >> 2) + t * 8;
        __syncwarp();
        #pragma unroll
        for (int j = 0; j < 8; j++) {
            int rr = j * 4 + rlo;
            float4 xv = __ldg(x4 + (size_t)(rowBase + rr) * 256 + eb4 + (lane & 7));
            xtw[(c4 + 0) * 32 + (rr ^ (c4 + 0))] = xv.x;
            xtw[(c4 + 1) * 32 + (rr ^ (c4 + 1))] = xv.y;
            xtw[(c4 + 2) * 32 + (rr ^ (c4 + 2))] = xv.z;
            xtw[(c4 + 3) * 32 + (rr ^ (c4 + 3))] = xv.w;
        }
        __syncwarp();
        #pragma unroll
        for (int el = 0; el < 32; el++) {
            float xv = xtw[el * 32 + (lane ^ el)];
            unsigned long long xx = pack2(xv, xv);
            int e = t * 32 + el;
            ulonglong2 q0 = sBu[e * 4 + 0];
            ulonglong2 q1 = sBu[e * 4 + 1];
            ulonglong2 q2 = sBu[e * 4 + 2];
            ulonglong2 q3 = sBu[e * 4 + 3];
            acc[0] = fma2(q0.x, xx, acc[0]);
            acc[1] = fma2(q0.y, xx, acc[1]);
            acc[2] = fma2(q1.x, xx, acc[2]);
            acc[3] = fma2(q1.y, xx, acc[3]);
            acc[4] = fma2(q2.x, xx, acc[4]);
            acc[5] = fma2(q2.y, xx, acc[5]);
            acc[6] = fma2(q3.x, xx, acc[6]);
            acc[7] = fma2(q3.y, xx, acc[7]);
        }
    }

    const int row = rowBase + lane;
    float v[16];
    #pragma unroll
    for (int j = 0; j < 8; j++) unpack2(acc[j], v[2 * j], v[2 * j + 1]);
    float4* gp = (float4*)(&g_bxp[blockIdx.y][row * D_STATE]);
    #pragma unroll
    for (int q = 0; q < 4; q++)
        gp[q] = make_float4(v[4 * q], v[4 * q + 1], v[4 * q + 2], v[4 * q + 3]);
}

// =======================================================================
// K1.5: sum partials, softplus, decay, AND per-chunk aggregates.
// =======================================================================
__global__ void __launch_bounds__(256) k_combine(const float* __restrict__ A)
{
    __shared__ float sbx[64 * 16 + 16];
    __shared__ float sdc[64 * 16 + 16];

    const int tid = threadIdx.x;
    const int idx = blockIdx.x * 256 + tid;   // float4 index
    float4 s = make_float4(0.f, 0.f, 0.f, 0.f);
    #pragma unroll
    for (int p = 0; p < ESPLIT; p++) {
        float4 v = __ldg((const float4*)g_bxp[p] + idx);
        s.x += v.x; s.y += v.y; s.z += v.z; s.w += v.w;
    }
    const int q = (idx & 3) * 4;
    float4 d;
    {
        float a0 = -expf(__ldg(A + q + 0));
        float a1 = -expf(__ldg(A + q + 1));
        float a2 = -expf(__ldg(A + q + 2));
        float a3 = -expf(__ldg(A + q + 3));
        float sp;
        sp = fmaxf(s.x, 0.f) + log1pf(expf(-fabsf(s.x))); d.x = expf(sp * a0);
        sp = fmaxf(s.y, 0.f) + log1pf(expf(-fabsf(s.y))); d.y = expf(sp * a1);
        sp = fmaxf(s.z, 0.f) + log1pf(expf(-fabsf(s.z))); d.z = expf(sp * a2);
        sp = fmaxf(s.w, 0.f) + log1pf(expf(-fabsf(s.w))); d.w = expf(sp * a3);
    }
    ((float4*)g_bx)[idx]    = s;
    ((float4*)g_decay)[idx] = d;

    const int rl  = tid >> 2;
    const int off = rl * 16 + ((tid & 3) * 4) + (rl >= 32 ? 16 : 0);
    *(float4*)&sbx[off] = s;
    *(float4*)&sdc[off] = d;
    __syncthreads();

    if (tid < 32) {
        const int cl = tid >> 4;
        const int st = tid & 15;
        const int base = cl * (32 * 16 + 16) + st;
        float a = 1.0f, v = 0.0f;
        #pragma unroll 8
        for (int t = 0; t < CHUNK2; t++) {
            float dd = sdc[base + t * 16];
            float bb = sbx[base + t * 16];
            v = fmaf(v, dd, bb);
            a *= dd;
        }
        const int r0 = blockIdx.x * 64;
        const int b  = r0 >> 12;
        const int cc = ((r0 & (SEQLEN - 1)) >> 5) + cl;
        const int gi = (b * NCHUNK2 + cc) * 16 + st;
        g_ca[gi] = a;
        g_cv[gi] = v;
    }
}

// =======================================================================
// K2b: boundary scan, 1 block per batch; smem-staged serial chain.
// =======================================================================
__global__ void __launch_bounds__(256) k_scan2()
{
    __shared__ float sa[NCHUNK2 * D_STATE];   // 8 KB
    __shared__ float sv[NCHUNK2 * D_STATE];   // 8 KB
    const int b   = blockIdx.x;
    const int tid = threadIdx.x;

    const float4* ga = (const float4*)(g_ca + b * NCHUNK2 * D_STATE);
    const float4* gv = (const float4*)(g_cv + b * NCHUNK2 * D_STATE);
    #pragma unroll
    for (int i = tid; i < (NCHUNK2 * D_STATE) / 4; i += 256) {
        ((float4*)sa)[i] = __ldg(ga + i);
        ((float4*)sv)[i] = __ldg(gv + i);
    }
    __syncthreads();

    if (tid < 16) {
        const int base = b * NCHUNK2 * D_STATE + tid;
        float h = 0.0f;
        #pragma unroll 8
        for (int cc = 0; cc < NCHUNK2; cc++) {
            g_h0[base + cc * D_STATE] = h;
            h = fmaf(sa[cc * D_STATE + tid], h, sv[cc * D_STATE + tid]);
        }
    }
}

// =======================================================================
// K3: per-chunk local scan + y = h @ C + x*D
// grid 1024 x 256; 2 cols/thread. f32x2 lanes = STATE PAIRS (2p,2p+1)
// of ONE column: h pairs are contiguous in hh -> 4 broadcast LDS.128/t,
// no pack2 MOVs, no duplicated bytes (R10/R13/R16 triplet evidence:
// duration tracks LDS wavefronts + issue slots jointly).
// =======================================================================
__global__ void __launch_bounds__(256, 4) k_out(const float* __restrict__ x,
                                                const float* __restrict__ C,
                                                const float* __restrict__ D,
                                                float* __restrict__ y)
{
    __shared__ __align__(16) float hh[CHUNK2][16];
    const int idx  = blockIdx.x;
    const int half = idx & 1;
    const int c    = (idx >> 1) & 127;
    const int b    = idx >> 8;
    const int tid  = threadIdx.x;
    const int row0 = b * SEQLEN + c * CHUNK2;
    const int col0 = half * 512 + tid * 2;

    // ---- issue scan loads FIRST (overlap with C-tile load latency) ----
    float h = 0.0f, dA[8], vA[8];
    int sbase = 0;
    if (tid < 16) {
        h = g_h0[(b * NCHUNK2 + c) * 16 + tid];
        sbase = row0 * D_STATE + tid;
        #pragma unroll
        for (int k = 0; k < 8; k++) {
            dA[k] = g_decay[sbase + k * 16];
            vA[k] = g_bx   [sbase + k * 16];
        }
    }

    // C tile repacked per column: ca0[p]=(C[2p][c0],C[2p+1][c0]),
    //                              ca1[p]=(C[2p][c0+1],C[2p+1][c0+1])
    unsigned long long ca0[8], ca1[8];
    #pragma unroll
    for (int p = 0; p < 8; p++) {
        float2 cv0 = __ldg((const float2*)(C + (2 * p)     * D_MODEL + col0));
        float2 cv1 = __ldg((const float2*)(C + (2 * p + 1) * D_MODEL + col0));
        ca0[p] = pack2(cv0.x, cv1.x);
        ca1[p] = pack2(cv0.y, cv1.y);
    }
    float2 dv = __ldg((const float2*)(D + col0));
    bool anyD = (dv.x != 0.0f) || (dv.y != 0.0f);

    // local 32-step scan by lanes 0..15 (scalar STS.32, conflict-free)
    if (tid < 16) {
        float dB[8], vB[8];
        #pragma unroll
        for (int g = 0; g < 4; g++) {
            if (g < 3) {
                #pragma unroll
                for (int k = 0; k < 8; k++) {
                    dB[k] = g_decay[sbase + ((g + 1) * 8 + k) * 16];
                    vB[k] = g_bx   [sbase + ((g + 1) * 8 + k) * 16];
                }
            }
            #pragma unroll
            for (int k = 0; k < 8; k++) {
                h = fmaf(h, dA[k], vA[k]);
                hh[g * 8 + k][tid] = h;
            }
            #pragma unroll
            for (int k = 0; k < 8; k++) { dA[k] = dB[k]; vA[k] = vB[k]; }
        }
    }
    __syncthreads();

    #pragma unroll 2
    for (int t = 0; t < CHUNK2; t++) {
        const ulonglong2* hp = (const ulonglong2*)hh[t];  // broadcast LDS.128
        ulonglong2 qa = hp[0];          // (h0,h1),(h2,h3)
        ulonglong2 qb = hp[1];          // (h4,h5),(h6,h7)

        unsigned long long a0 = mul2(qa.x, ca0[0]);   // col0 accum (state-pair lanes)
        unsigned long long a1 = mul2(qa.x, ca1[0]);   // col0+1 accum
        a0 = fma2(qa.y, ca0[1], a0);
        a1 = fma2(qa.y, ca1[1], a1);
        a0 = fma2(qb.x, ca0[2], a0);
        a1 = fma2(qb.x, ca1[2], a1);
        a0 = fma2(qb.y, ca0[3], a0);
        a1 = fma2(qb.y, ca1[3], a1);
        qa = hp[2];                     // (h8,h9),(h10,h11)
        qb = hp[3];                     // (h12,h13),(h14,h15)
        a0 = fma2(qa.x, ca0[4], a0);
        a1 = fma2(qa.x, ca1[4], a1);
        a0 = fma2(qa.y, ca0[5], a0);
        a1 = fma2(qa.y, ca1[5], a1);
        a0 = fma2(qb.x, ca0[6], a0);
        a1 = fma2(qb.x, ca1[6], a1);
        a0 = fma2(qb.y, ca0[7], a0);
        a1 = fma2(qb.y, ca1[7], a1);

        float l0, h0v, l1, h1v;
        unpack2(a0, l0, h0v);
        unpack2(a1, l1, h1v);
        float2 out;
        out.x = l0 + h0v;
        out.y = l1 + h1v;
        if (anyD) {
            float2 xv = __ldg((const float2*)(x + (size_t)(row0 + t) * D_MODEL + col0));
            out.x = fmaf(xv.x, dv.x, out.x);
            out.y = fmaf(xv.y, dv.y, out.y);
        }
        *(float2*)(y + (size_t)(row0 + t) * D_MODEL + col0) = out;
    }
}

// =======================================================================
extern "C" void kernel_launch(void* const* d_in, const int* in_sizes, int n_in,
                              void* d_out, int out_size)
{
    const float* x   = (const float*)d_in[0];
    const float* A   = (const float*)d_in[1];
    const float* Bin = (const float*)d_in[2];
    const float* C   = (const float*)d_in[3];
    const float* D   = (const float*)d_in[4];
    float* y = (float*)d_out;

    dim3 g1(NROWS / 256, ESPLIT);
    k_bx<<<g1, 256>>>(x, Bin);
    k_combine<<<(NROWS * 4) / 256, 256>>>(A);
    k_scan2<<<BATCH, 256>>>();
    k_out<<<BATCH * NCHUNK2 * 2, 256>>>(x, C, D, y);
}